// round 2
// baseline (speedup 1.0000x reference)
#include <cuda_runtime.h>
#include <math.h>

#define N 8192
#define D 64
#define ALPHA 0.2f
#define NB 4096          // value bins
#define NCHUNK 32
#define CHUNK 256        // N / NCHUNK

// ---------------- scratch ----------------
__device__ float g_h[N * D];
__device__ float g_f1[N];
__device__ float g_f2[N];
__device__ float g_fmin, g_fmax, g_scale;
__device__ int   g_binStart[NB + 1];
__device__ float g_f2s[N];          // bucket-sorted f2 (sorted by (bin, orig idx))
__device__ int   g_idx[N];
__device__ float g_p[N];            // e^{f2-fmax}
__device__ float g_q[N];            // e^{a(f2-fmax)}
__device__ float g_csumP[NCHUNK * D];
__device__ float g_csumQ[NCHUNK * D];
__device__ float g_csp[NCHUNK], g_csq[NCHUNK];
__device__ float g_offP[NCHUNK * D], g_offQ[NCHUNK * D];
__device__ float g_offPs[NCHUNK], g_offQs[NCHUNK];
__device__ float g_Cpos[(N + 1) * D];   // inclusive suffix of p*h
__device__ float g_Cneg[(N + 1) * D];   // exclusive prefix of q*h
__device__ float g_Dpos[N + 1], g_Dneg[N + 1];

__device__ __forceinline__ int bin_of(float v, float fmin, float scale) {
    int b = (int)((v - fmin) * scale);
    return b < 0 ? 0 : (b > NB - 1 ? NB - 1 : b);
}

// ---------------- K1: h = x@Wt, f1, f2 ----------------
// 128 blocks x 256 threads, 64 rows per block (W loaded once per block)
__global__ void k_feat(const float* __restrict__ x, const float* __restrict__ Wt,
                       const float* __restrict__ a1, const float* __restrict__ b1,
                       const float* __restrict__ a2, const float* __restrict__ b2) {
    __shared__ float sW[D * D];
    __shared__ float sx[4][D];
    __shared__ float s1[8], s2[8];

    int t = threadIdx.x;
    for (int i = t; i < D * D; i += 256) sW[i] = Wt[i];
    int r = t >> 6;
    int o = t & 63;
    float A1 = a1[o], A2 = a2[o];
    float B1 = b1[0], B2 = b2[0];

    for (int it = 0; it < 16; it++) {
        int row = blockIdx.x * 64 + it * 4 + r;
        __syncthreads();
        sx[r][o] = x[row * D + o];
        __syncthreads();

        float h = 0.f;
#pragma unroll
        for (int i = 0; i < D; i++) h = fmaf(sx[r][i], sW[i * D + o], h);
        g_h[row * D + o] = h;

        float v1 = h * A1;
        float v2 = h * A2;
#pragma unroll
        for (int s = 16; s; s >>= 1) {
            v1 += __shfl_xor_sync(0xFFFFFFFFu, v1, s);
            v2 += __shfl_xor_sync(0xFFFFFFFFu, v2, s);
        }
        if ((t & 31) == 0) { s1[t >> 5] = v1; s2[t >> 5] = v2; }
        __syncthreads();
        if (o == 0) {
            g_f1[row] = s1[2 * r] + s1[2 * r + 1] + B1;
            g_f2[row] = s2[2 * r] + s2[2 * r + 1] + B2;
        }
    }
}

// ---------------- K2: minmax + histogram + scan + scatter + per-bin sort + p/q ----------------
// single block, 1024 threads
__global__ void k_bucket() {
    __shared__ int sh_bs[NB + 1];    // bin starts
    __shared__ int sh_off[NB];       // hist, then scatter cursors
    __shared__ float sred[64];
    __shared__ int swsum[32];

    int t = threadIdx.x;

    // --- min / max of f2 ---
    float mn = INFINITY, mx = -INFINITY;
    for (int i = t; i < N; i += 1024) {
        float v = g_f2[i];
        mn = fminf(mn, v); mx = fmaxf(mx, v);
    }
#pragma unroll
    for (int s = 16; s; s >>= 1) {
        mn = fminf(mn, __shfl_xor_sync(0xFFFFFFFFu, mn, s));
        mx = fmaxf(mx, __shfl_xor_sync(0xFFFFFFFFu, mx, s));
    }
    if ((t & 31) == 0) { sred[t >> 5] = mn; sred[32 + (t >> 5)] = mx; }
    __syncthreads();
    if (t == 0) {
        float a = INFINITY, b = -INFINITY;
        for (int w = 0; w < 32; w++) { a = fminf(a, sred[w]); b = fmaxf(b, sred[32 + w]); }
        float range = fmaxf(b - a, 1e-20f);
        g_fmin = a; g_fmax = b; g_scale = (float)NB / range;
        sred[0] = a; sred[1] = b; sred[2] = (float)NB / range;
    }
    __syncthreads();
    float fmin = sred[0], fmax = sred[1], scale = sred[2];

    // --- histogram ---
    for (int i = t; i < NB; i += 1024) sh_off[i] = 0;
    __syncthreads();
    for (int i = t; i < N; i += 1024)
        atomicAdd(&sh_off[bin_of(g_f2[i], fmin, scale)], 1);
    __syncthreads();

    // --- exclusive scan of histogram (4 bins / thread) ---
    int h4[4];
    int base4 = t * 4;
    int sum = 0;
#pragma unroll
    for (int j = 0; j < 4; j++) { h4[j] = sh_off[base4 + j]; sum += h4[j]; }
    int incl = sum;
#pragma unroll
    for (int s = 1; s < 32; s <<= 1) {
        int v = __shfl_up_sync(0xFFFFFFFFu, incl, s);
        if ((t & 31) >= s) incl += v;
    }
    if ((t & 31) == 31) swsum[t >> 5] = incl;
    __syncthreads();
    if (t < 32) {
        int v = swsum[t];
        int inc = v;
#pragma unroll
        for (int s = 1; s < 32; s <<= 1) {
            int u = __shfl_up_sync(0xFFFFFFFFu, inc, s);
            if (t >= s) inc += u;
        }
        swsum[t] = inc - v;   // exclusive warp offset
    }
    __syncthreads();
    int run = swsum[t >> 5] + (incl - sum);
#pragma unroll
    for (int j = 0; j < 4; j++) { sh_bs[base4 + j] = run; run += h4[j]; }
    if (t == 0) sh_bs[NB] = N;
    __syncthreads();

    // publish binStart, init scatter cursors
    for (int i = t; i < NB; i += 1024) { g_binStart[i] = sh_bs[i]; sh_off[i] = sh_bs[i]; }
    if (t == 0) g_binStart[NB] = N;
    __syncthreads();

    // --- scatter ---
    for (int i = t; i < N; i += 1024) {
        float f = g_f2[i];
        int b = bin_of(f, fmin, scale);
        int pos = atomicAdd(&sh_off[b], 1);
        g_f2s[pos] = f;
        g_idx[pos] = i;
    }
    __syncthreads();

    // --- per-bin insertion sort by original index (determinism) + p/q ---
    for (int b = t; b < NB; b += 1024) {
        int s0 = sh_bs[b], e0 = sh_bs[b + 1];
        for (int i = s0 + 1; i < e0; i++) {
            int ki = g_idx[i]; float kf = g_f2s[i];
            int j = i - 1;
            while (j >= s0 && g_idx[j] > ki) {
                g_idx[j + 1] = g_idx[j]; g_f2s[j + 1] = g_f2s[j]; j--;
            }
            g_idx[j + 1] = ki; g_f2s[j + 1] = kf;
        }
        for (int k = s0; k < e0; k++) {
            float d = g_f2s[k] - fmax;
            g_p[k] = expf(d);
            g_q[k] = expf(ALPHA * d);
        }
    }
}

// ---------------- K3: per-chunk partial sums ----------------
// 32 blocks x 256 threads
__global__ void k_chunks() {
    __shared__ float sP[4][64], sQ[4][64];
    __shared__ float sw[16];
    int t = threadIdx.x;
    int o = t & 63, r = t >> 6;
    int k0 = blockIdx.x * CHUNK;

    float aP = 0.f, aQ = 0.f;
    for (int m = r; m < CHUNK; m += 4) {
        int k = k0 + m;
        float hv = g_h[g_idx[k] * D + o];
        aP = fmaf(g_p[k], hv, aP);
        aQ = fmaf(g_q[k], hv, aQ);
    }
    sP[r][o] = aP; sQ[r][o] = aQ;

    // scalar sums
    float sp = g_p[k0 + t];
    float sq = g_q[k0 + t];
#pragma unroll
    for (int s = 16; s; s >>= 1) {
        sp += __shfl_xor_sync(0xFFFFFFFFu, sp, s);
        sq += __shfl_xor_sync(0xFFFFFFFFu, sq, s);
    }
    if ((t & 31) == 0) { sw[t >> 5] = sp; sw[8 + (t >> 5)] = sq; }
    __syncthreads();

    if (r == 0) {
        g_csumP[blockIdx.x * 64 + o] = sP[0][o] + sP[1][o] + sP[2][o] + sP[3][o];
        g_csumQ[blockIdx.x * 64 + o] = sQ[0][o] + sQ[1][o] + sQ[2][o] + sQ[3][o];
    }
    if (t == 0) {
        float a = 0.f, b = 0.f;
        for (int w = 0; w < 8; w++) { a += sw[w]; b += sw[8 + w]; }
        g_csp[blockIdx.x] = a;
        g_csq[blockIdx.x] = b;
    }
}

// ---------------- K4: chunk offsets (prefix for Q, suffix for P) ----------------
__global__ void k_offsets() {
    int t = threadIdx.x;   // 96, active < 65
    if (t < 64) {
        float run = 0.f;
        for (int c = 0; c < NCHUNK; c++) { g_offQ[c * 64 + t] = run; run += g_csumQ[c * 64 + t]; }
        run = 0.f;
        for (int c = NCHUNK - 1; c >= 0; c--) { g_offP[c * 64 + t] = run; run += g_csumP[c * 64 + t]; }
    } else if (t == 64) {
        float run = 0.f;
        for (int c = 0; c < NCHUNK; c++) { g_offQs[c] = run; run += g_csq[c]; }
        run = 0.f;
        for (int c = NCHUNK - 1; c >= 0; c--) { g_offPs[c] = run; run += g_csp[c]; }
    }
}

// ---------------- K5: sequential walk per chunk -> C arrays (all coalesced) ----------------
// 64 blocks (32 chunks x 2 directions) x 96 threads
__global__ void k_prefix() {
    int t = threadIdx.x;
    int chunk = blockIdx.x >> 1;
    int dir = blockIdx.x & 1;
    int k0 = chunk * CHUNK;

    if (dir == 0) {          // forward: exclusive prefix of q*h
        if (t < 64) {
            float run = g_offQ[chunk * 64 + t];
#pragma unroll 4
            for (int m = 0; m < CHUNK; m++) {
                int k = k0 + m;
                g_Cneg[k * D + t] = run;
                run = fmaf(g_q[k], g_h[g_idx[k] * D + t], run);
            }
            if (chunk == NCHUNK - 1) g_Cneg[N * D + t] = run;
        } else if (t == 64) {
            float run = g_offQs[chunk];
            for (int m = 0; m < CHUNK; m++) { int k = k0 + m; g_Dneg[k] = run; run += g_q[k]; }
            if (chunk == NCHUNK - 1) g_Dneg[N] = run;
        }
    } else {                 // backward: inclusive suffix of p*h
        if (t < 64) {
            float run = g_offP[chunk * 64 + t];
            if (chunk == NCHUNK - 1) g_Cpos[N * D + t] = 0.f;
#pragma unroll 4
            for (int m = CHUNK - 1; m >= 0; m--) {
                int k = k0 + m;
                run = fmaf(g_p[k], g_h[g_idx[k] * D + t], run);
                g_Cpos[k * D + t] = run;
            }
        } else if (t == 64) {
            float run = g_offPs[chunk];
            if (chunk == NCHUNK - 1) g_Dpos[N] = 0.f;
            for (int m = CHUNK - 1; m >= 0; m--) { int k = k0 + m; run += g_p[k]; g_Dpos[k] = run; }
        }
    }
}

// ---------------- K6: per-row combine + exact boundary bin + ELU ----------------
__global__ void k_out(float* __restrict__ out) {
    int t = threadIdx.x;                 // 256, 4 rows/block
    int row = blockIdx.x * 4 + (t >> 6);
    int o = t & 63;

    float f1 = g_f1[row];
    float fmax = g_fmax, fmin = g_fmin, scale = g_scale;
    float s0 = f1 + fmax;
    float m = (s0 >= 0.f) ? s0 : ALPHA * s0;
    float A = expf(s0 - m);
    float B = expf(ALPHA * s0 - m);
    float thr = -f1;

    int b = bin_of(thr, fmin, scale);
    int bs = g_binStart[b];
    int be = g_binStart[b + 1];

    float num = A * g_Cpos[be * D + o] + B * g_Cneg[bs * D + o];
    float den = A * g_Dpos[be] + B * g_Dneg[bs];

    for (int j = bs; j < be; j++) {      // exact compares within boundary bin
        float f2j = g_f2s[j];
        float hv = g_h[g_idx[j] * D + o];
        if (f2j >= thr) { float w = A * g_p[j]; num = fmaf(w, hv, num); den += w; }
        else            { float w = B * g_q[j]; num = fmaf(w, hv, num); den += w; }
    }

    float ret = num / den;
    out[row * D + o] = (ret > 0.f) ? ret : expm1f(ret);
}

// ---------------- launch ----------------
extern "C" void kernel_launch(void* const* d_in, const int* in_sizes, int n_in,
                              void* d_out, int out_size) {
    const float* x  = (const float*)d_in[0];
    const float* Wt = (const float*)d_in[1];
    const float* a1 = (const float*)d_in[2];
    const float* b1 = (const float*)d_in[3];
    const float* a2 = (const float*)d_in[4];
    const float* b2 = (const float*)d_in[5];
    float* out = (float*)d_out;

    k_feat<<<128, 256>>>(x, Wt, a1, b1, a2, b2);
    k_bucket<<<1, 1024>>>();
    k_chunks<<<32, 256>>>();
    k_offsets<<<1, 96>>>();
    k_prefix<<<64, 96>>>();
    k_out<<<2048, 256>>>(out);
}

// round 3
// speedup vs baseline: 1.5919x; 1.5919x over previous
#include <cuda_runtime.h>
#include <math.h>

#define N 8192
#define D 64
#define ALPHA 0.2f
#define NB 4096          // value bins
#define NCHUNK 64
#define CHUNK 128        // N / NCHUNK

// ---------------- scratch ----------------
__device__ float g_h[N * D];
__device__ float g_f1[N];
__device__ float g_f2[N];
__device__ float g_fmin, g_fmax, g_scale;
__device__ int   g_binStart[NB + 1];
__device__ float g_f2s[N];          // bucket-sorted f2 (by (bin, orig idx))
__device__ int   g_idx[N];
__device__ float g_p[N];            // e^{f2-fmax}
__device__ float g_q[N];            // e^{a(f2-fmax)}
__device__ float g_csumP[NCHUNK * D];
__device__ float g_csumQ[NCHUNK * D];
__device__ float g_csp[NCHUNK], g_csq[NCHUNK];
__device__ float g_Cpos[(N + 1) * D];   // inclusive suffix of p*h
__device__ float g_Cneg[(N + 1) * D];   // exclusive prefix of q*h
__device__ float g_Dpos[N + 1], g_Dneg[N + 1];

__device__ __forceinline__ int bin_of(float v, float fmin, float scale) {
    int b = (int)((v - fmin) * scale);
    return b < 0 ? 0 : (b > NB - 1 ? NB - 1 : b);
}

// ---------------- K1: h = x@Wt, f1, f2 ----------------
// 128 blocks x 256 threads, 64 rows per block
__global__ void k_feat(const float* __restrict__ x, const float* __restrict__ Wt,
                       const float* __restrict__ a1, const float* __restrict__ b1,
                       const float* __restrict__ a2, const float* __restrict__ b2) {
    __shared__ float sW[D * D];
    __shared__ float sx[4][D];
    __shared__ float s1[8], s2[8];

    int t = threadIdx.x;
    for (int i = t; i < D * D; i += 256) sW[i] = Wt[i];
    int r = t >> 6;
    int o = t & 63;
    float A1 = a1[o], A2 = a2[o];
    float B1 = b1[0], B2 = b2[0];

    for (int it = 0; it < 16; it++) {
        int row = blockIdx.x * 64 + it * 4 + r;
        __syncthreads();
        sx[r][o] = x[row * D + o];
        __syncthreads();

        float h = 0.f;
#pragma unroll
        for (int i = 0; i < D; i++) h = fmaf(sx[r][i], sW[i * D + o], h);
        g_h[row * D + o] = h;

        float v1 = h * A1;
        float v2 = h * A2;
#pragma unroll
        for (int s = 16; s; s >>= 1) {
            v1 += __shfl_xor_sync(0xFFFFFFFFu, v1, s);
            v2 += __shfl_xor_sync(0xFFFFFFFFu, v2, s);
        }
        if ((t & 31) == 0) { s1[t >> 5] = v1; s2[t >> 5] = v2; }
        __syncthreads();
        if (o == 0) {
            g_f1[row] = s1[2 * r] + s1[2 * r + 1] + B1;
            g_f2[row] = s2[2 * r] + s2[2 * r + 1] + B2;
        }
    }
}

// ---------------- K2: minmax + histogram + scan + scatter + per-bin sort + p/q ----------------
// single block, 1024 threads
__global__ void k_bucket() {
    __shared__ int sh_bs[NB + 1];
    __shared__ int sh_off[NB];
    __shared__ float sred[64];
    __shared__ int swsum[32];

    int t = threadIdx.x;

    // --- min / max of f2 ---
    float mn = INFINITY, mx = -INFINITY;
#pragma unroll
    for (int u = 0; u < 8; u++) {
        float v = g_f2[t + u * 1024];
        mn = fminf(mn, v); mx = fmaxf(mx, v);
    }
#pragma unroll
    for (int s = 16; s; s >>= 1) {
        mn = fminf(mn, __shfl_xor_sync(0xFFFFFFFFu, mn, s));
        mx = fmaxf(mx, __shfl_xor_sync(0xFFFFFFFFu, mx, s));
    }
    if ((t & 31) == 0) { sred[t >> 5] = mn; sred[32 + (t >> 5)] = mx; }
    __syncthreads();
    if (t == 0) {
        float a = INFINITY, b = -INFINITY;
#pragma unroll
        for (int w = 0; w < 32; w++) { a = fminf(a, sred[w]); b = fmaxf(b, sred[32 + w]); }
        float range = fmaxf(b - a, 1e-20f);
        g_fmin = a; g_fmax = b; g_scale = (float)NB / range;
        sred[0] = a; sred[1] = b; sred[2] = (float)NB / range;
    }
    __syncthreads();
    float fmin = sred[0], fmax = sred[1], scale = sred[2];

    // --- histogram ---
    for (int i = t; i < NB; i += 1024) sh_off[i] = 0;
    __syncthreads();
#pragma unroll
    for (int u = 0; u < 8; u++)
        atomicAdd(&sh_off[bin_of(g_f2[t + u * 1024], fmin, scale)], 1);
    __syncthreads();

    // --- exclusive scan of histogram (4 bins / thread) ---
    int h4[4];
    int base4 = t * 4;
    int sum = 0;
#pragma unroll
    for (int j = 0; j < 4; j++) { h4[j] = sh_off[base4 + j]; sum += h4[j]; }
    int incl = sum;
#pragma unroll
    for (int s = 1; s < 32; s <<= 1) {
        int v = __shfl_up_sync(0xFFFFFFFFu, incl, s);
        if ((t & 31) >= s) incl += v;
    }
    if ((t & 31) == 31) swsum[t >> 5] = incl;
    __syncthreads();
    if (t < 32) {
        int v = swsum[t];
        int inc = v;
#pragma unroll
        for (int s = 1; s < 32; s <<= 1) {
            int u = __shfl_up_sync(0xFFFFFFFFu, inc, s);
            if (t >= s) inc += u;
        }
        swsum[t] = inc - v;
    }
    __syncthreads();
    int run = swsum[t >> 5] + (incl - sum);
#pragma unroll
    for (int j = 0; j < 4; j++) { sh_bs[base4 + j] = run; run += h4[j]; }
    if (t == 0) sh_bs[NB] = N;
    __syncthreads();

    for (int i = t; i < NB; i += 1024) { g_binStart[i] = sh_bs[i]; sh_off[i] = sh_bs[i]; }
    if (t == 0) g_binStart[NB] = N;
    __syncthreads();

    // --- scatter ---
#pragma unroll
    for (int u = 0; u < 8; u++) {
        int i = t + u * 1024;
        float f = g_f2[i];
        int b = bin_of(f, fmin, scale);
        int pos = atomicAdd(&sh_off[b], 1);
        g_f2s[pos] = f;
        g_idx[pos] = i;
    }
    __syncthreads();

    // --- per-bin insertion sort by original index (determinism) + p/q ---
    for (int b = t; b < NB; b += 1024) {
        int s0 = sh_bs[b], e0 = sh_bs[b + 1];
        for (int i = s0 + 1; i < e0; i++) {
            int ki = g_idx[i]; float kf = g_f2s[i];
            int j = i - 1;
            while (j >= s0 && g_idx[j] > ki) {
                g_idx[j + 1] = g_idx[j]; g_f2s[j + 1] = g_f2s[j]; j--;
            }
            g_idx[j + 1] = ki; g_f2s[j + 1] = kf;
        }
        for (int k = s0; k < e0; k++) {
            float d = g_f2s[k] - fmax;
            g_p[k] = expf(d);
            g_q[k] = expf(ALPHA * d);
        }
    }
}

// ---------------- K3: per-chunk partial sums ----------------
// NCHUNK blocks x 256 threads
__global__ void k_chunks() {
    __shared__ float sP[4][64], sQ[4][64];
    __shared__ float sw[8];
    int t = threadIdx.x;
    int o = t & 63, r = t >> 6;
    int k0 = blockIdx.x * CHUNK;

    float aP = 0.f, aQ = 0.f;
#pragma unroll 8
    for (int m = r; m < CHUNK; m += 4) {
        int k = k0 + m;
        float hv = g_h[g_idx[k] * D + o];
        aP = fmaf(g_p[k], hv, aP);
        aQ = fmaf(g_q[k], hv, aQ);
    }
    sP[r][o] = aP; sQ[r][o] = aQ;

    // scalar sums over CHUNK=128 elements (threads 0..127)
    float sp = 0.f, sq = 0.f;
    if (t < CHUNK) { sp = g_p[k0 + t]; sq = g_q[k0 + t]; }
#pragma unroll
    for (int s = 16; s; s >>= 1) {
        sp += __shfl_xor_sync(0xFFFFFFFFu, sp, s);
        sq += __shfl_xor_sync(0xFFFFFFFFu, sq, s);
    }
    if (t < CHUNK && (t & 31) == 0) { sw[t >> 5] = sp; sw[4 + (t >> 5)] = sq; }
    __syncthreads();

    if (r == 0) {
        g_csumP[blockIdx.x * 64 + o] = sP[0][o] + sP[1][o] + sP[2][o] + sP[3][o];
        g_csumQ[blockIdx.x * 64 + o] = sQ[0][o] + sQ[1][o] + sQ[2][o] + sQ[3][o];
    }
    if (t == 0) {
        g_csp[blockIdx.x] = sw[0] + sw[1] + sw[2] + sw[3];
        g_csq[blockIdx.x] = sw[4] + sw[5] + sw[6] + sw[7];
    }
}

// ---------------- K4: per-chunk walk; offset computed in-block (all loads parallel) ----------------
// 2*NCHUNK blocks x 128 threads
__global__ void k_prefix() {
    int t = threadIdx.x;
    int chunk = blockIdx.x >> 1;
    int dir = blockIdx.x & 1;
    int k0 = chunk * CHUNK;

    if (dir == 0) {          // forward: exclusive prefix of q*h
        if (t < 64) {
            float off = 0.f;
#pragma unroll
            for (int c = 0; c < NCHUNK; c++) {
                float v = g_csumQ[c * 64 + t];
                if (c < chunk) off += v;
            }
            float run = off;
#pragma unroll 8
            for (int m = 0; m < CHUNK; m++) {
                int k = k0 + m;
                g_Cneg[k * D + t] = run;
                run = fmaf(g_q[k], g_h[g_idx[k] * D + t], run);
            }
            if (chunk == NCHUNK - 1) g_Cneg[N * D + t] = run;
        } else if (t == 64) {
            float off = 0.f;
#pragma unroll
            for (int c = 0; c < NCHUNK; c++) {
                float v = g_csq[c];
                if (c < chunk) off += v;
            }
            float run = off;
            for (int m = 0; m < CHUNK; m++) { int k = k0 + m; g_Dneg[k] = run; run += g_q[k]; }
            if (chunk == NCHUNK - 1) g_Dneg[N] = run;
        }
    } else {                 // backward: inclusive suffix of p*h
        if (t < 64) {
            float off = 0.f;
#pragma unroll
            for (int c = 0; c < NCHUNK; c++) {
                float v = g_csumP[c * 64 + t];
                if (c > chunk) off += v;
            }
            float run = off;
            if (chunk == NCHUNK - 1) g_Cpos[N * D + t] = 0.f;
#pragma unroll 8
            for (int m = CHUNK - 1; m >= 0; m--) {
                int k = k0 + m;
                run = fmaf(g_p[k], g_h[g_idx[k] * D + t], run);
                g_Cpos[k * D + t] = run;
            }
        } else if (t == 64) {
            float off = 0.f;
#pragma unroll
            for (int c = 0; c < NCHUNK; c++) {
                float v = g_csp[c];
                if (c > chunk) off += v;
            }
            float run = off;
            if (chunk == NCHUNK - 1) g_Dpos[N] = 0.f;
            for (int m = CHUNK - 1; m >= 0; m--) { int k = k0 + m; run += g_p[k]; g_Dpos[k] = run; }
        }
    }
}

// ---------------- K5: per-row combine + exact boundary bin + ELU ----------------
__global__ void k_out(float* __restrict__ out) {
    int t = threadIdx.x;                 // 256, 4 rows/block
    int row = blockIdx.x * 4 + (t >> 6);
    int o = t & 63;

    float f1 = g_f1[row];
    float fmax = g_fmax, fmin = g_fmin, scale = g_scale;
    float s0 = f1 + fmax;
    float m = (s0 >= 0.f) ? s0 : ALPHA * s0;
    float A = expf(s0 - m);
    float B = expf(ALPHA * s0 - m);
    float thr = -f1;

    int b = bin_of(thr, fmin, scale);
    int bs = g_binStart[b];
    int be = g_binStart[b + 1];

    float num = A * g_Cpos[be * D + o] + B * g_Cneg[bs * D + o];
    float den = A * g_Dpos[be] + B * g_Dneg[bs];

    for (int j = bs; j < be; j++) {      // exact compares within boundary bin
        float f2j = g_f2s[j];
        float hv = g_h[g_idx[j] * D + o];
        if (f2j >= thr) { float w = A * g_p[j]; num = fmaf(w, hv, num); den += w; }
        else            { float w = B * g_q[j]; num = fmaf(w, hv, num); den += w; }
    }

    float ret = num / den;
    out[row * D + o] = (ret > 0.f) ? ret : expm1f(ret);
}

// ---------------- launch ----------------
extern "C" void kernel_launch(void* const* d_in, const int* in_sizes, int n_in,
                              void* d_out, int out_size) {
    const float* x  = (const float*)d_in[0];
    const float* Wt = (const float*)d_in[1];
    const float* a1 = (const float*)d_in[2];
    const float* b1 = (const float*)d_in[3];
    const float* a2 = (const float*)d_in[4];
    const float* b2 = (const float*)d_in[5];
    float* out = (float*)d_out;

    k_feat<<<128, 256>>>(x, Wt, a1, b1, a2, b2);
    k_bucket<<<1, 1024>>>();
    k_chunks<<<NCHUNK, 256>>>();
    k_prefix<<<2 * NCHUNK, 128>>>();
    k_out<<<2048, 256>>>(out);
}

// round 4
// speedup vs baseline: 2.3212x; 1.4582x over previous
#include <cuda_runtime.h>
#include <math.h>

#define N 8192
#define D 64
#define ALPHA 0.2f
#define NB 4096          // value bins
#define NCHUNK 64
#define CHUNK 128        // N / NCHUNK

// ---------------- scratch ----------------
__device__ float g_h[N * D];
__device__ float g_f1[N];
__device__ float g_f2[N];
__device__ float g_fmin, g_fmax, g_scale;
__device__ int   g_binStart[NB + 1];
__device__ float g_f2s[N];          // bucket-sorted f2 (by (bin, orig idx))
__device__ int   g_idx[N];
__device__ float g_p[N];            // e^{f2-fmax}
__device__ float g_q[N];            // e^{a(f2-fmax)}
__device__ float g_P[N * D];        // p*h in sorted order
__device__ float g_Q[N * D];        // q*h in sorted order
__device__ float g_csumP[NCHUNK * D];
__device__ float g_csumQ[NCHUNK * D];
__device__ float g_csp[NCHUNK], g_csq[NCHUNK];
__device__ float g_Cpos[(N + 1) * D];   // inclusive suffix of p*h
__device__ float g_Cneg[(N + 1) * D];   // exclusive prefix of q*h
__device__ float g_Dpos[N + 1], g_Dneg[N + 1];

__device__ __forceinline__ int bin_of(float v, float fmin, float scale) {
    int b = (int)((v - fmin) * scale);
    return b < 0 ? 0 : (b > NB - 1 ? NB - 1 : b);
}

// ---------------- K1: h = x@Wt, f1, f2 (x row double-buffered) ----------------
// 128 blocks x 256 threads, 64 rows per block
__global__ void k_feat(const float* __restrict__ x, const float* __restrict__ Wt,
                       const float* __restrict__ a1, const float* __restrict__ b1,
                       const float* __restrict__ a2, const float* __restrict__ b2) {
    __shared__ float sW[D * D];
    __shared__ float sx[4][D];
    __shared__ float s1[8], s2[8];

    int t = threadIdx.x;
    for (int i = t; i < D * D; i += 256) sW[i] = Wt[i];
    int r = t >> 6;
    int o = t & 63;
    float A1 = a1[o], A2 = a2[o];
    float B1 = b1[0], B2 = b2[0];

    int row0 = blockIdx.x * 64 + r;
    float xv = x[row0 * D + o];             // prefetch iter 0

    for (int it = 0; it < 16; it++) {
        int row = blockIdx.x * 64 + it * 4 + r;
        __syncthreads();                    // previous compute done with sx
        sx[r][o] = xv;
        __syncthreads();
        if (it + 1 < 16) xv = x[(row + 4) * D + o];   // prefetch next

        float h = 0.f;
#pragma unroll
        for (int i = 0; i < D; i++) h = fmaf(sx[r][i], sW[i * D + o], h);
        g_h[row * D + o] = h;

        float v1 = h * A1;
        float v2 = h * A2;
#pragma unroll
        for (int s = 16; s; s >>= 1) {
            v1 += __shfl_xor_sync(0xFFFFFFFFu, v1, s);
            v2 += __shfl_xor_sync(0xFFFFFFFFu, v2, s);
        }
        if ((t & 31) == 0) { s1[t >> 5] = v1; s2[t >> 5] = v2; }
        __syncthreads();
        if (o == 0) {
            g_f1[row] = s1[2 * r] + s1[2 * r + 1] + B1;
            g_f2[row] = s2[2 * r] + s2[2 * r + 1] + B2;
        }
    }
}

// ---------------- K2: minmax + histogram + scan + scatter + per-bin sort ----------------
// single block, 1024 threads
__global__ void k_bucket() {
    __shared__ int sh_bs[NB + 1];
    __shared__ int sh_off[NB];
    __shared__ float sred[64];
    __shared__ int swsum[32];

    int t = threadIdx.x;

    // --- min / max of f2 ---
    float mn = INFINITY, mx = -INFINITY;
#pragma unroll
    for (int u = 0; u < 8; u++) {
        float v = g_f2[t + u * 1024];
        mn = fminf(mn, v); mx = fmaxf(mx, v);
    }
#pragma unroll
    for (int s = 16; s; s >>= 1) {
        mn = fminf(mn, __shfl_xor_sync(0xFFFFFFFFu, mn, s));
        mx = fmaxf(mx, __shfl_xor_sync(0xFFFFFFFFu, mx, s));
    }
    if ((t & 31) == 0) { sred[t >> 5] = mn; sred[32 + (t >> 5)] = mx; }
    __syncthreads();
    if (t == 0) {
        float a = INFINITY, b = -INFINITY;
#pragma unroll
        for (int w = 0; w < 32; w++) { a = fminf(a, sred[w]); b = fmaxf(b, sred[32 + w]); }
        float range = fmaxf(b - a, 1e-20f);
        g_fmin = a; g_fmax = b; g_scale = (float)NB / range;
        sred[0] = a; sred[2] = (float)NB / range;
    }
    __syncthreads();
    float fmin = sred[0], scale = sred[2];

    // --- histogram ---
    for (int i = t; i < NB; i += 1024) sh_off[i] = 0;
    __syncthreads();
#pragma unroll
    for (int u = 0; u < 8; u++)
        atomicAdd(&sh_off[bin_of(g_f2[t + u * 1024], fmin, scale)], 1);
    __syncthreads();

    // --- exclusive scan of histogram (4 bins / thread) ---
    int h4[4];
    int base4 = t * 4;
    int sum = 0;
#pragma unroll
    for (int j = 0; j < 4; j++) { h4[j] = sh_off[base4 + j]; sum += h4[j]; }
    int incl = sum;
#pragma unroll
    for (int s = 1; s < 32; s <<= 1) {
        int v = __shfl_up_sync(0xFFFFFFFFu, incl, s);
        if ((t & 31) >= s) incl += v;
    }
    if ((t & 31) == 31) swsum[t >> 5] = incl;
    __syncthreads();
    if (t < 32) {
        int v = swsum[t];
        int inc = v;
#pragma unroll
        for (int s = 1; s < 32; s <<= 1) {
            int u = __shfl_up_sync(0xFFFFFFFFu, inc, s);
            if (t >= s) inc += u;
        }
        swsum[t] = inc - v;
    }
    __syncthreads();
    int run = swsum[t >> 5] + (incl - sum);
#pragma unroll
    for (int j = 0; j < 4; j++) { sh_bs[base4 + j] = run; run += h4[j]; }
    if (t == 0) sh_bs[NB] = N;
    __syncthreads();

    for (int i = t; i < NB; i += 1024) { g_binStart[i] = sh_bs[i]; sh_off[i] = sh_bs[i]; }
    if (t == 0) g_binStart[NB] = N;
    __syncthreads();

    // --- scatter ---
#pragma unroll
    for (int u = 0; u < 8; u++) {
        int i = t + u * 1024;
        float f = g_f2[i];
        int b = bin_of(f, fmin, scale);
        int pos = atomicAdd(&sh_off[b], 1);
        g_f2s[pos] = f;
        g_idx[pos] = i;
    }
    __syncthreads();

    // --- per-bin insertion sort by original index (determinism) ---
    for (int b = t; b < NB; b += 1024) {
        int s0 = sh_bs[b], e0 = sh_bs[b + 1];
        for (int i = s0 + 1; i < e0; i++) {
            int ki = g_idx[i]; float kf = g_f2s[i];
            int j = i - 1;
            while (j >= s0 && g_idx[j] > ki) {
                g_idx[j + 1] = g_idx[j]; g_f2s[j + 1] = g_f2s[j]; j--;
            }
            g_idx[j + 1] = ki; g_f2s[j + 1] = kf;
        }
    }
}

// ---------------- K3: p/q + gather + materialize P/Q + chunk sums ----------------
// NCHUNK blocks x 256 threads
__global__ void k_chunks() {
    __shared__ float sp[CHUNK], sq[CHUNK];
    __shared__ float sP[4][64], sQ[4][64];
    __shared__ float sw[8];
    int t = threadIdx.x;
    int o = t & 63, r = t >> 6;
    int k0 = blockIdx.x * CHUNK;

    float fmax = g_fmax;
    if (t < CHUNK) {
        float d = g_f2s[k0 + t] - fmax;
        float pv = expf(d), qv = expf(ALPHA * d);
        sp[t] = pv; sq[t] = qv;
        g_p[k0 + t] = pv; g_q[k0 + t] = qv;
    }
    __syncthreads();

    float aP = 0.f, aQ = 0.f;
#pragma unroll 8
    for (int m = r; m < CHUNK; m += 4) {
        int k = k0 + m;
        float hv = g_h[g_idx[k] * D + o];
        float Pv = sp[m] * hv;
        float Qv = sq[m] * hv;
        g_P[k * D + o] = Pv;
        g_Q[k * D + o] = Qv;
        aP += Pv; aQ += Qv;
    }
    sP[r][o] = aP; sQ[r][o] = aQ;

    float spv = 0.f, sqv = 0.f;
    if (t < CHUNK) { spv = sp[t]; sqv = sq[t]; }
#pragma unroll
    for (int s = 16; s; s >>= 1) {
        spv += __shfl_xor_sync(0xFFFFFFFFu, spv, s);
        sqv += __shfl_xor_sync(0xFFFFFFFFu, sqv, s);
    }
    if (t < CHUNK && (t & 31) == 0) { sw[t >> 5] = spv; sw[4 + (t >> 5)] = sqv; }
    __syncthreads();

    if (r == 0) {
        g_csumP[blockIdx.x * 64 + o] = sP[0][o] + sP[1][o] + sP[2][o] + sP[3][o];
        g_csumQ[blockIdx.x * 64 + o] = sQ[0][o] + sQ[1][o] + sQ[2][o] + sQ[3][o];
    }
    if (t == 0) {
        g_csp[blockIdx.x] = sw[0] + sw[1] + sw[2] + sw[3];
        g_csq[blockIdx.x] = sw[4] + sw[5] + sw[6] + sw[7];
    }
}

// ---------------- K4: smem-staged prefix+suffix walks (both dirs per block) ----------------
// NCHUNK blocks x 256 threads; dynamic smem = 2*CHUNK*64*4 + 2*CHUNK*4 bytes
__global__ void k_prefix() {
    extern __shared__ float sm[];
    float* sPc = sm;                        // CHUNK*64
    float* sQc = sm + CHUNK * 64;           // CHUNK*64
    float* sps = sm + 2 * CHUNK * 64;       // CHUNK
    float* sqs = sps + CHUNK;               // CHUNK

    int t = threadIdx.x;
    int chunk = blockIdx.x;
    int k0 = chunk * CHUNK;

    // coalesced bulk load of the chunk's P and Q (float4, high MLP)
    {
        const float4* srcP = (const float4*)(g_P + (size_t)k0 * D);
        const float4* srcQ = (const float4*)(g_Q + (size_t)k0 * D);
        float4* dP = (float4*)sPc;
        float4* dQ = (float4*)sQc;
#pragma unroll
        for (int i = t; i < CHUNK * 16; i += 256) { dP[i] = srcP[i]; dQ[i] = srcQ[i]; }
        if (t < CHUNK) { sps[t] = g_p[k0 + t]; sqs[t] = g_q[k0 + t]; }
    }
    __syncthreads();

    if (t < 64) {
        // forward: exclusive prefix of Q, column t
        float off = 0.f;
#pragma unroll
        for (int c = 0; c < NCHUNK; c++) {
            float v = g_csumQ[c * 64 + t];
            if (c < chunk) off += v;
        }
        float run = off;
#pragma unroll 8
        for (int m = 0; m < CHUNK; m++) {
            g_Cneg[(size_t)(k0 + m) * D + t] = run;
            run += sQc[m * 64 + t];
        }
        if (chunk == NCHUNK - 1) g_Cneg[(size_t)N * D + t] = run;
    } else if (t < 128) {
        // backward: inclusive suffix of P, column t-64
        int c0 = t - 64;
        float off = 0.f;
#pragma unroll
        for (int c = 0; c < NCHUNK; c++) {
            float v = g_csumP[c * 64 + c0];
            if (c > chunk) off += v;
        }
        float run = off;
        if (chunk == NCHUNK - 1) g_Cpos[(size_t)N * D + c0] = 0.f;
#pragma unroll 8
        for (int m = CHUNK - 1; m >= 0; m--) {
            run += sPc[m * 64 + c0];
            g_Cpos[(size_t)(k0 + m) * D + c0] = run;
        }
    } else if (t == 128) {
        float off = 0.f;
#pragma unroll
        for (int c = 0; c < NCHUNK; c++) { float v = g_csq[c]; if (c < chunk) off += v; }
        float run = off;
        for (int m = 0; m < CHUNK; m++) { g_Dneg[k0 + m] = run; run += sqs[m]; }
        if (chunk == NCHUNK - 1) g_Dneg[N] = run;
    } else if (t == 129) {
        float off = 0.f;
#pragma unroll
        for (int c = 0; c < NCHUNK; c++) { float v = g_csp[c]; if (c > chunk) off += v; }
        float run = off;
        if (chunk == NCHUNK - 1) g_Dpos[N] = 0.f;
        for (int m = CHUNK - 1; m >= 0; m--) { run += sps[m]; g_Dpos[k0 + m] = run; }
    }
}

// ---------------- K5: per-row combine + exact boundary bin + ELU ----------------
__global__ void k_out(float* __restrict__ out) {
    int t = threadIdx.x;                 // 256, 4 rows/block
    int row = blockIdx.x * 4 + (t >> 6);
    int o = t & 63;

    float f1 = g_f1[row];
    float fmax = g_fmax, fmin = g_fmin, scale = g_scale;
    float s0 = f1 + fmax;
    float m = (s0 >= 0.f) ? s0 : ALPHA * s0;
    float A = expf(s0 - m);
    float B = expf(ALPHA * s0 - m);
    float thr = -f1;

    int b = bin_of(thr, fmin, scale);
    int bs = g_binStart[b];
    int be = g_binStart[b + 1];

    float num = A * g_Cpos[(size_t)be * D + o] + B * g_Cneg[(size_t)bs * D + o];
    float den = A * g_Dpos[be] + B * g_Dneg[bs];

    for (int j = bs; j < be; j++) {      // exact compares within boundary bin
        float f2j = g_f2s[j];
        float hv = g_h[g_idx[j] * D + o];
        if (f2j >= thr) { float w = A * g_p[j]; num = fmaf(w, hv, num); den += w; }
        else            { float w = B * g_q[j]; num = fmaf(w, hv, num); den += w; }
    }

    float ret = num / den;
    out[row * D + o] = (ret > 0.f) ? ret : expm1f(ret);
}

// ---------------- launch ----------------
extern "C" void kernel_launch(void* const* d_in, const int* in_sizes, int n_in,
                              void* d_out, int out_size) {
    const float* x  = (const float*)d_in[0];
    const float* Wt = (const float*)d_in[1];
    const float* a1 = (const float*)d_in[2];
    const float* b1 = (const float*)d_in[3];
    const float* a2 = (const float*)d_in[4];
    const float* b2 = (const float*)d_in[5];
    float* out = (float*)d_out;

    const int smem_prefix = 2 * CHUNK * 64 * 4 + 2 * CHUNK * 4;
    cudaFuncSetAttribute(k_prefix, cudaFuncAttributeMaxDynamicSharedMemorySize, smem_prefix);

    k_feat<<<128, 256>>>(x, Wt, a1, b1, a2, b2);
    k_bucket<<<1, 1024>>>();
    k_chunks<<<NCHUNK, 256>>>();
    k_prefix<<<NCHUNK, 256, smem_prefix>>>();
    k_out<<<2048, 256>>>(out);
}

// round 5
// speedup vs baseline: 2.7294x; 1.1758x over previous
#include <cuda_runtime.h>
#include <math.h>

#define N 8192
#define D 64
#define ALPHA 0.2f
#define NB 4096          // value bins
#define NCHUNK 64
#define CHUNK 128        // N / NCHUNK

// ---------------- scratch ----------------
__device__ float g_h[N * D];
__device__ float g_f1[N];
__device__ float g_f2[N];
__device__ float g_fmin, g_fmax, g_scale;
__device__ int   g_binStart[NB + 1];
__device__ float g_f2s[N];          // bucket-sorted f2 (by (bin, orig idx))
__device__ int   g_idx[N];
__device__ float g_p[N];            // e^{f2-fmax}
__device__ float g_q[N];            // e^{a(f2-fmax)}
__device__ float g_csumP[NCHUNK * D];
__device__ float g_csumQ[NCHUNK * D];
__device__ float g_csp[NCHUNK], g_csq[NCHUNK];
__device__ float g_Cpos[(N + 1) * D];   // inclusive suffix of p*h
__device__ float g_Cneg[(N + 1) * D];   // exclusive prefix of q*h
__device__ float g_Dpos[N + 1], g_Dneg[N + 1];

// barrier counters (reset by their users each replay)
__device__ int g_c1 = 0;
__device__ int g_c2 = 0;
__device__ int g_c2done = 0;

__device__ __forceinline__ int bin_of(float v, float fmin, float scale) {
    int b = (int)((v - fmin) * scale);
    return b < 0 ? 0 : (b > NB - 1 ? NB - 1 : b);
}

// =============== K1: feat (all 128 blocks) + bucket (block 0) ===============
// 128 blocks x 1024 threads; dynamic smem overlaid:
//   feat view  : sW[4096] | sx[1024] | s12[64]                (20.8 KB)
//   bucket view: bs[NB+1] | off[NB] | sred[64] | swsum[32]    (33.2 KB)
__global__ void k_feat_bucket(const float* __restrict__ x, const float* __restrict__ Wt,
                              const float* __restrict__ a1, const float* __restrict__ b1,
                              const float* __restrict__ a2, const float* __restrict__ b2) {
    extern __shared__ float sm[];
    int t = threadIdx.x;

    // ---------------- feat phase ----------------
    {
        float* sW  = sm;             // 4096
        float* sx  = sm + 4096;      // 1024 (16 rows x 64)
        float* s12 = sm + 5120;      // 64

        int r = t >> 6;              // 0..15
        int o = t & 63;
#pragma unroll
        for (int u = 0; u < 4; u++) sW[t + u * 1024] = Wt[t + u * 1024];
        float A1 = a1[o], A2 = a2[o];
        float B1 = b1[0], B2 = b2[0];

        int row_base = blockIdx.x * 64;
        float xv = x[(row_base + r) * D + o];

        for (int it = 0; it < 4; it++) {
            int row = row_base + it * 16 + r;
            __syncthreads();
            sx[r * 64 + o] = xv;
            __syncthreads();
            if (it < 3) xv = x[(row + 16) * D + o];

            float h = 0.f;
#pragma unroll
            for (int i = 0; i < D; i++) h = fmaf(sx[r * 64 + i], sW[i * 64 + o], h);
            g_h[row * D + o] = h;

            float v1 = h * A1;
            float v2 = h * A2;
#pragma unroll
            for (int s = 16; s; s >>= 1) {
                v1 += __shfl_xor_sync(0xFFFFFFFFu, v1, s);
                v2 += __shfl_xor_sync(0xFFFFFFFFu, v2, s);
            }
            int w = t >> 5;
            if ((t & 31) == 0) { s12[w] = v1; s12[32 + w] = v2; }
            __syncthreads();
            if (o == 0) {
                g_f1[row] = s12[2 * r] + s12[2 * r + 1] + B1;
                g_f2[row] = s12[32 + 2 * r] + s12[32 + 2 * r + 1] + B2;
            }
        }
    }

    // ---------------- grid arrival ----------------
    __syncthreads();
    __threadfence();
    if (t == 0) atomicAdd(&g_c1, 1);
    if (blockIdx.x != 0) return;

    if (t == 0) {
        while (atomicAdd(&g_c1, 0) < 128) __nanosleep(64);
        atomicExch(&g_c1, 0);         // reset for next replay (sole reader done)
    }
    __syncthreads();

    // ---------------- bucket phase (block 0, 1024 threads) ----------------
    int* sh_bs   = (int*)sm;                 // NB+1
    int* sh_off  = (int*)sm + (NB + 1);      // NB
    float* sred  = (float*)((int*)sm + (2 * NB + 1));  // 64
    int* swsum   = (int*)sm + (2 * NB + 1) + 64;       // 32

    // --- min / max of f2 ---
    float mn = INFINITY, mx = -INFINITY;
#pragma unroll
    for (int u = 0; u < 8; u++) {
        float v = g_f2[t + u * 1024];
        mn = fminf(mn, v); mx = fmaxf(mx, v);
    }
#pragma unroll
    for (int s = 16; s; s >>= 1) {
        mn = fminf(mn, __shfl_xor_sync(0xFFFFFFFFu, mn, s));
        mx = fmaxf(mx, __shfl_xor_sync(0xFFFFFFFFu, mx, s));
    }
    if ((t & 31) == 0) { sred[t >> 5] = mn; sred[32 + (t >> 5)] = mx; }
    __syncthreads();
    if (t == 0) {
        float a = INFINITY, b = -INFINITY;
#pragma unroll
        for (int w = 0; w < 32; w++) { a = fminf(a, sred[w]); b = fmaxf(b, sred[32 + w]); }
        float range = fmaxf(b - a, 1e-20f);
        g_fmin = a; g_fmax = b; g_scale = (float)NB / range;
        sred[0] = a; sred[2] = (float)NB / range;
    }
    __syncthreads();
    float fmin = sred[0], scale = sred[2];

    // --- histogram ---
    for (int i = t; i < NB; i += 1024) sh_off[i] = 0;
    __syncthreads();
#pragma unroll
    for (int u = 0; u < 8; u++)
        atomicAdd(&sh_off[bin_of(g_f2[t + u * 1024], fmin, scale)], 1);
    __syncthreads();

    // --- exclusive scan of histogram (4 bins / thread) ---
    int h4[4];
    int base4 = t * 4;
    int sum = 0;
#pragma unroll
    for (int j = 0; j < 4; j++) { h4[j] = sh_off[base4 + j]; sum += h4[j]; }
    int incl = sum;
#pragma unroll
    for (int s = 1; s < 32; s <<= 1) {
        int v = __shfl_up_sync(0xFFFFFFFFu, incl, s);
        if ((t & 31) >= s) incl += v;
    }
    if ((t & 31) == 31) swsum[t >> 5] = incl;
    __syncthreads();
    if (t < 32) {
        int v = swsum[t];
        int inc = v;
#pragma unroll
        for (int s = 1; s < 32; s <<= 1) {
            int u = __shfl_up_sync(0xFFFFFFFFu, inc, s);
            if (t >= s) inc += u;
        }
        swsum[t] = inc - v;
    }
    __syncthreads();
    int run = swsum[t >> 5] + (incl - sum);
#pragma unroll
    for (int j = 0; j < 4; j++) { sh_bs[base4 + j] = run; run += h4[j]; }
    if (t == 0) sh_bs[NB] = N;
    __syncthreads();

    for (int i = t; i < NB; i += 1024) { g_binStart[i] = sh_bs[i]; sh_off[i] = sh_bs[i]; }
    if (t == 0) g_binStart[NB] = N;
    __syncthreads();

    // --- scatter ---
#pragma unroll
    for (int u = 0; u < 8; u++) {
        int i = t + u * 1024;
        float f = g_f2[i];
        int b = bin_of(f, fmin, scale);
        int pos = atomicAdd(&sh_off[b], 1);
        g_f2s[pos] = f;
        g_idx[pos] = i;
    }
    __syncthreads();

    // --- per-bin insertion sort by original index (determinism) ---
    for (int b = t; b < NB; b += 1024) {
        int s0 = sh_bs[b], e0 = sh_bs[b + 1];
        for (int i = s0 + 1; i < e0; i++) {
            int ki = g_idx[i]; float kf = g_f2s[i];
            int j = i - 1;
            while (j >= s0 && g_idx[j] > ki) {
                g_idx[j + 1] = g_idx[j]; g_f2s[j + 1] = g_f2s[j]; j--;
            }
            g_idx[j + 1] = ki; g_f2s[j + 1] = kf;
        }
    }
}

// =============== K2: chunk sums + grid barrier + prefix/suffix walk ===============
// NCHUNK blocks x 256 threads; dyn smem: sPc[8192] | sQc[8192] | sps[128] | sqs[128]
__global__ void k_scanfused() {
    extern __shared__ float sm2[];
    float* sPc = sm2;                       // CHUNK*64
    float* sQc = sm2 + CHUNK * 64;          // CHUNK*64
    float* sps = sm2 + 2 * CHUNK * 64;      // CHUNK
    float* sqs = sps + CHUNK;               // CHUNK
    __shared__ float sP[4][64], sQ[4][64], sw[8];

    int t = threadIdx.x;
    int o = t & 63, r = t >> 6;
    int chunk = blockIdx.x;
    int k0 = chunk * CHUNK;

    // ---- phase A: p/q + gather + P/Q into smem + chunk sums ----
    float fmax = g_fmax;
    if (t < CHUNK) {
        float d = g_f2s[k0 + t] - fmax;
        float pv = expf(d), qv = expf(ALPHA * d);
        sps[t] = pv; sqs[t] = qv;
        g_p[k0 + t] = pv; g_q[k0 + t] = qv;
    }
    __syncthreads();

    float aP = 0.f, aQ = 0.f;
#pragma unroll 8
    for (int m = r; m < CHUNK; m += 4) {
        int k = k0 + m;
        float hv = g_h[g_idx[k] * D + o];
        float Pv = sps[m] * hv;
        float Qv = sqs[m] * hv;
        sPc[m * 64 + o] = Pv;
        sQc[m * 64 + o] = Qv;
        aP += Pv; aQ += Qv;
    }
    sP[r][o] = aP; sQ[r][o] = aQ;

    float spv = 0.f, sqv = 0.f;
    if (t < CHUNK) { spv = sps[t]; sqv = sqs[t]; }
#pragma unroll
    for (int s = 16; s; s >>= 1) {
        spv += __shfl_xor_sync(0xFFFFFFFFu, spv, s);
        sqv += __shfl_xor_sync(0xFFFFFFFFu, sqv, s);
    }
    if (t < CHUNK && (t & 31) == 0) { sw[t >> 5] = spv; sw[4 + (t >> 5)] = sqv; }
    __syncthreads();

    if (r == 0) {
        g_csumP[chunk * 64 + o] = sP[0][o] + sP[1][o] + sP[2][o] + sP[3][o];
        g_csumQ[chunk * 64 + o] = sQ[0][o] + sQ[1][o] + sQ[2][o] + sQ[3][o];
    }
    if (t == 0) {
        g_csp[chunk] = sw[0] + sw[1] + sw[2] + sw[3];
        g_csq[chunk] = sw[4] + sw[5] + sw[6] + sw[7];
    }

    // ---- grid barrier (all 64 blocks resident: 64 < 148 SMs) ----
    __syncthreads();
    __threadfence();
    if (t == 0) {
        atomicAdd(&g_c2, 1);
        while (atomicAdd(&g_c2, 0) < NCHUNK) __nanosleep(64);
    }
    __syncthreads();

    // ---- phase B: offsets + walks (from smem) ----
    if (t < 64) {
        float off = 0.f;
#pragma unroll
        for (int c = 0; c < NCHUNK; c++) {
            float v = g_csumQ[c * 64 + t];
            if (c < chunk) off += v;
        }
        float run = off;
#pragma unroll 8
        for (int m = 0; m < CHUNK; m++) {
            g_Cneg[(size_t)(k0 + m) * D + t] = run;
            run += sQc[m * 64 + t];
        }
        if (chunk == NCHUNK - 1) g_Cneg[(size_t)N * D + t] = run;
    } else if (t < 128) {
        int c0 = t - 64;
        float off = 0.f;
#pragma unroll
        for (int c = 0; c < NCHUNK; c++) {
            float v = g_csumP[c * 64 + c0];
            if (c > chunk) off += v;
        }
        float run = off;
        if (chunk == NCHUNK - 1) g_Cpos[(size_t)N * D + c0] = 0.f;
#pragma unroll 8
        for (int m = CHUNK - 1; m >= 0; m--) {
            run += sPc[m * 64 + c0];
            g_Cpos[(size_t)(k0 + m) * D + c0] = run;
        }
    } else if (t == 128) {
        float off = 0.f;
#pragma unroll
        for (int c = 0; c < NCHUNK; c++) { float v = g_csq[c]; if (c < chunk) off += v; }
        float run = off;
        for (int m = 0; m < CHUNK; m++) { g_Dneg[k0 + m] = run; run += sqs[m]; }
        if (chunk == NCHUNK - 1) g_Dneg[N] = run;
    } else if (t == 129) {
        float off = 0.f;
#pragma unroll
        for (int c = 0; c < NCHUNK; c++) { float v = g_csp[c]; if (c > chunk) off += v; }
        float run = off;
        if (chunk == NCHUNK - 1) g_Dpos[N] = 0.f;
        for (int m = CHUNK - 1; m >= 0; m--) { run += sps[m]; g_Dpos[k0 + m] = run; }
    }

    // ---- replay-safe counter reset (last block out resets both) ----
    __syncthreads();
    if (t == 0) {
        int d = atomicAdd(&g_c2done, 1);
        if (d == NCHUNK - 1) {
            atomicExch(&g_c2, 0);
            atomicExch(&g_c2done, 0);
        }
    }
}

// =============== K3: per-row combine + exact boundary bin + ELU ===============
__global__ void k_out(float* __restrict__ out) {
    int t = threadIdx.x;                 // 256, 4 rows/block
    int row = blockIdx.x * 4 + (t >> 6);
    int o = t & 63;

    float f1 = g_f1[row];
    float fmax = g_fmax, fmin = g_fmin, scale = g_scale;
    float s0 = f1 + fmax;
    float m = (s0 >= 0.f) ? s0 : ALPHA * s0;
    float A = expf(s0 - m);
    float B = expf(ALPHA * s0 - m);
    float thr = -f1;

    int b = bin_of(thr, fmin, scale);
    int bs = g_binStart[b];
    int be = g_binStart[b + 1];

    float num = A * g_Cpos[(size_t)be * D + o] + B * g_Cneg[(size_t)bs * D + o];
    float den = A * g_Dpos[be] + B * g_Dneg[bs];

    for (int j = bs; j < be; j++) {      // exact compares within boundary bin
        float f2j = g_f2s[j];
        float hv = g_h[g_idx[j] * D + o];
        if (f2j >= thr) { float w = A * g_p[j]; num = fmaf(w, hv, num); den += w; }
        else            { float w = B * g_q[j]; num = fmaf(w, hv, num); den += w; }
    }

    float ret = num / den;
    out[row * D + o] = (ret > 0.f) ? ret : expm1f(ret);
}

// ---------------- launch ----------------
extern "C" void kernel_launch(void* const* d_in, const int* in_sizes, int n_in,
                              void* d_out, int out_size) {
    const float* x  = (const float*)d_in[0];
    const float* Wt = (const float*)d_in[1];
    const float* a1 = (const float*)d_in[2];
    const float* b1 = (const float*)d_in[3];
    const float* a2 = (const float*)d_in[4];
    const float* b2 = (const float*)d_in[5];
    float* out = (float*)d_out;

    const int smem_k1 = ((2 * NB + 1) + 64 + 32) * 4;          // bucket view (33.2 KB) > feat view
    const int smem_k2 = (2 * CHUNK * 64 + 2 * CHUNK) * 4;      // 66.5 KB

    static bool attr_set = false;
    if (!attr_set) {
        cudaFuncSetAttribute(k_feat_bucket, cudaFuncAttributeMaxDynamicSharedMemorySize, smem_k1);
        cudaFuncSetAttribute(k_scanfused, cudaFuncAttributeMaxDynamicSharedMemorySize, smem_k2);
        attr_set = true;
    }

    k_feat_bucket<<<128, 1024, smem_k1>>>(x, Wt, a1, b1, a2, b2);
    k_scanfused<<<NCHUNK, 256, smem_k2>>>();
    k_out<<<2048, 256>>>(out);
}